// round 1
// baseline (speedup 1.0000x reference)
#include <cuda_runtime.h>
#include <cstdint>

#define BB 256
#define TT 100
#define CC 40
#define H1 1024
#define H2 512
#define OO 35
#define MT (BB*TT)

#define NBLK 148
#define NTHR 1024

// ---------------- static device scratch (no cudaMalloc allowed) ----------------
__device__ float g_P1[(size_t)MT * H1];      // ~100 MB: precomputed input drive (BN-folded)
__device__ float g_Wd_s[H1 * CC];            // W_delay * scale1 (row-major [H1][C])
__device__ float g_shift1[H1];
__device__ float g_shift2[H2];
__device__ float g_Wr1T[H1 * H1];            // [in][out], * scale1[out]
__device__ float g_W2T [H1 * H2];            // [in][out], * scale2[out]
__device__ float g_Wr2T[H2 * H2];            // [in][out], * scale2[out]
__device__ float g_WoT [H2 * OO];            // [in][out]
__device__ int   g_fli[CC];
__device__ float g_frac[CC];

__device__ float g_v1[BB*H1], g_a1[BB*H1], g_s1[BB*H1];
__device__ float g_v2[BB*H2], g_a2[BB*H2], g_s2[BB*H2];
__device__ float g_vo[BB*OO], g_acc[BB*OO];
__device__ int   g_list1[2][BB*H1];
__device__ int   g_list2[2][BB*H2];
__device__ int   g_cnt1[2][BB];
__device__ int   g_cnt2[2][BB];
__device__ unsigned g_bar_cnt;
__device__ unsigned g_bar_gen;

// ---------------- prep: fold BN, transpose weights, delay params, zero state ----
__global__ void prep_kernel(const float* __restrict__ delay_raw,
                            const float* __restrict__ W_delay,
                            const float* __restrict__ W_rec1,
                            const float* __restrict__ W2,
                            const float* __restrict__ W_rec2,
                            const float* __restrict__ W_out,
                            const float* __restrict__ g1, const float* __restrict__ b1,
                            const float* __restrict__ m1, const float* __restrict__ v1,
                            const float* __restrict__ g2, const float* __restrict__ b2,
                            const float* __restrict__ m2, const float* __restrict__ v2)
{
    const int gtid = blockIdx.x * blockDim.x + threadIdx.x;
    const int nth  = gridDim.x * blockDim.x;

    for (int c = gtid; c < CC; c += nth) {
        float xr = delay_raw[c];
        float s  = (xr >= 0.0f) ? (1.0f / (1.0f + expf(-xr)))
                                : (expf(xr) / (1.0f + expf(xr)));
        float d  = s * 30.0f;              // MAX_DELAY
        float fl = floorf(d);
        g_fli[c]  = (int)fl;
        g_frac[c] = d - fl;
    }
    for (int i = gtid; i < H1*CC; i += nth) {
        int h = i / CC;
        float sc = g1[h] * rsqrtf(v1[h] + 1e-5f);
        g_Wd_s[i] = W_delay[i] * sc;
    }
    for (int h = gtid; h < H1; h += nth) {
        float sc = g1[h] * rsqrtf(v1[h] + 1e-5f);
        g_shift1[h] = b1[h] - m1[h] * sc;
    }
    for (int h = gtid; h < H2; h += nth) {
        float sc = g2[h] * rsqrtf(v2[h] + 1e-5f);
        g_shift2[h] = b2[h] - m2[h] * sc;
    }
    for (int i = gtid; i < H1*H1; i += nth) {
        int o = i / H1, h = i - o*H1;
        float sc = g1[o] * rsqrtf(v1[o] + 1e-5f);
        g_Wr1T[h*H1 + o] = W_rec1[i] * sc;
    }
    for (int i = gtid; i < H2*H1; i += nth) {   // W2 is [H2][H1]
        int o = i / H1, h = i - o*H1;
        float sc = g2[o] * rsqrtf(v2[o] + 1e-5f);
        g_W2T[h*H2 + o] = W2[i] * sc;
    }
    for (int i = gtid; i < H2*H2; i += nth) {
        int o = i / H2, h = i - o*H2;
        float sc = g2[o] * rsqrtf(v2[o] + 1e-5f);
        g_Wr2T[h*H2 + o] = W_rec2[i] * sc;
    }
    for (int i = gtid; i < OO*H2; i += nth) {   // W_out is [O][H2]
        int o = i / H2, h = i - o*H2;
        g_WoT[h*OO + o] = W_out[i];
    }
    // zero state (required every launch for deterministic graph replays)
    for (int i = gtid; i < BB*H1; i += nth) { g_v1[i]=0.f; g_a1[i]=0.f; g_s1[i]=0.f; }
    for (int i = gtid; i < BB*H2; i += nth) { g_v2[i]=0.f; g_a2[i]=0.f; g_s2[i]=0.f; }
    for (int i = gtid; i < BB*OO; i += nth) { g_vo[i]=0.f; g_acc[i]=0.f; }
    for (int i = gtid; i < 2*BB; i += nth) {
        ((int*)g_cnt1)[i] = 0;
        ((int*)g_cnt2)[i] = 0;
    }
    if (gtid == 0) { g_bar_cnt = 0u; }
}

// ---------------- P1 = (delayed x) @ (W_delay*scale1)^T + shift1 ----------------
// rows r = t*256 + b  (matches P1[t][b][h] layout), 64x64 tile, K=40
__global__ __launch_bounds__(256) void gemm_p1_kernel(const float* __restrict__ x)
{
    __shared__ __align__(16) float xs[CC * 64];   // xs[k*64 + row]
    __shared__ __align__(16) float ws[CC * 64];   // ws[k*64 + col]

    const int r0 = blockIdx.y * 64;
    const int h0 = blockIdx.x * 64;

    for (int i = threadIdx.x; i < 64*CC; i += 256) {
        int h = i / CC, c = i - h*CC;
        ws[c*64 + h] = g_Wd_s[(h0 + h)*CC + c];
    }
    for (int i = threadIdx.x; i < 64*CC; i += 256) {
        int row = i / CC, c = i - row*CC;
        int r = r0 + row;
        int t = r >> 8;        // r / 256
        int b = r & 255;
        int i0 = t - g_fli[c];
        float fr = g_frac[c];
        float x0 = (i0 >= 0) ? x[(b*TT + i0    )*CC + c] : 0.0f;
        float x1 = (i0 >= 1) ? x[(b*TT + i0 - 1)*CC + c] : 0.0f;
        xs[c*64 + row] = (1.0f - fr)*x0 + fr*x1;
    }
    __syncthreads();

    const int ty = threadIdx.x >> 4;
    const int tx = threadIdx.x & 15;
    float acc[4][4];
    #pragma unroll
    for (int i = 0; i < 4; i++)
        #pragma unroll
        for (int j = 0; j < 4; j++) acc[i][j] = 0.0f;

    #pragma unroll
    for (int k = 0; k < CC; k++) {
        float4 a = *(const float4*)&xs[k*64 + ty*4];
        float4 w = *(const float4*)&ws[k*64 + tx*4];
        acc[0][0] += a.x*w.x; acc[0][1] += a.x*w.y; acc[0][2] += a.x*w.z; acc[0][3] += a.x*w.w;
        acc[1][0] += a.y*w.x; acc[1][1] += a.y*w.y; acc[1][2] += a.y*w.z; acc[1][3] += a.y*w.w;
        acc[2][0] += a.z*w.x; acc[2][1] += a.z*w.y; acc[2][2] += a.z*w.z; acc[2][3] += a.z*w.w;
        acc[3][0] += a.w*w.x; acc[3][1] += a.w*w.y; acc[3][2] += a.w*w.z; acc[3][3] += a.w*w.w;
    }

    const int hc = h0 + tx*4;
    float4 sh = *(const float4*)&g_shift1[hc];
    #pragma unroll
    for (int i = 0; i < 4; i++) {
        int r = r0 + ty*4 + i;
        float4 o;
        o.x = acc[i][0] + sh.x; o.y = acc[i][1] + sh.y;
        o.z = acc[i][2] + sh.z; o.w = acc[i][3] + sh.w;
        *(float4*)&g_P1[(size_t)r*H1 + hc] = o;
    }
}

// ---------------- grid barrier (148 co-resident CTAs) ---------------------------
__device__ __forceinline__ void grid_sync()
{
    __syncthreads();
    if (threadIdx.x == 0) {
        unsigned gen = *(volatile unsigned*)&g_bar_gen;
        __threadfence();
        if (atomicAdd(&g_bar_cnt, 1u) == (unsigned)(gridDim.x - 1)) {
            *(volatile unsigned*)&g_bar_cnt = 0u;
            __threadfence();
            atomicAdd(&g_bar_gen, 1u);
        } else {
            while (*(volatile unsigned*)&g_bar_gen == gen) { __nanosleep(32); }
        }
        __threadfence();
    }
    __syncthreads();
}

// ---------------- persistent time-stepping kernel --------------------------------
__global__ __launch_bounds__(NTHR, 1) void snn_step_kernel(
    float* __restrict__ out,
    const float* __restrict__ alpha1, const float* __restrict__ rho1, const float* __restrict__ beta_a1,
    const float* __restrict__ alpha2, const float* __restrict__ rho2, const float* __restrict__ beta_a2,
    const float* __restrict__ beta_out)
{
    const int gtid = blockIdx.x * NTHR + threadIdx.x;
    const int nth  = NBLK * NTHR;

    for (int t = 0; t < TT; t++) {
        const int q = t & 1, p = q ^ 1;

        // ---------- Phase A: readout for step t-1 (parity p) + layer-1 step t ----
        if (t > 0) {
            for (int e = gtid; e < BB*OO; e += nth) {
                int b = e / OO, o = e - b*OO;
                int n = g_cnt2[p][b];
                const int* lst = &g_list2[p][b*H2];
                float io = 0.0f;
                for (int j = 0; j < n; j++) io += g_WoT[lst[j]*OO + o];
                float bo  = beta_out[o];
                float von = bo * g_vo[e] + (1.0f - bo) * io;
                g_vo[e] = von;
                g_acc[e] += von;
            }
        }
        for (int i = gtid; i < BB; i += nth) g_cnt2[q][i] = 0;

        for (int e = gtid; e < BB*H1; e += nth) {
            int b = e >> 10, h = e & (H1-1);
            int n = g_cnt1[p][b];
            const int* lst = &g_list1[p][b*H1];
            float rec = 0.0f;
            for (int j = 0; j < n; j++) rec += g_Wr1T[lst[j]*H1 + h];
            float I1 = g_P1[(size_t)t*(BB*H1) + e] + rec;     // BN already folded
            float so = g_s1[e];
            float an = rho1[h]*g_a1[e] + beta_a1[h]*so;
            float al = alpha1[h];
            float vn = al*g_v1[e] + (1.0f - al)*I1 - an - so; // THRESH=1
            float sn = ((vn - 1.0f) >= 0.0f) ? 1.0f : 0.0f;
            g_a1[e] = an; g_v1[e] = vn; g_s1[e] = sn;
            if (sn != 0.0f) {
                int pos = atomicAdd(&g_cnt1[q][b], 1);
                g_list1[q][b*H1 + pos] = h;
            }
        }
        grid_sync();

        // ---------- Phase B: layer-2 step t ----------
        for (int i = gtid; i < BB; i += nth) g_cnt1[p][i] = 0;

        for (int e = gtid; e < BB*H2; e += nth) {
            int b = e >> 9, h = e & (H2-1);
            float u = 0.0f;
            int n1 = g_cnt1[q][b];
            const int* l1 = &g_list1[q][b*H1];
            for (int j = 0; j < n1; j++) u += g_W2T[l1[j]*H2 + h];
            int n2 = g_cnt2[p][b];
            const int* l2 = &g_list2[p][b*H2];
            for (int j = 0; j < n2; j++) u += g_Wr2T[l2[j]*H2 + h];
            float I2 = u + g_shift2[h];
            float so = g_s2[e];
            float an = rho2[h]*g_a2[e] + beta_a2[h]*so;
            float al = alpha2[h];
            float vn = al*g_v2[e] + (1.0f - al)*I2 - an - so;
            float sn = ((vn - 1.0f) >= 0.0f) ? 1.0f : 0.0f;
            g_a2[e] = an; g_v2[e] = vn; g_s2[e] = sn;
            if (sn != 0.0f) {
                int pos = atomicAdd(&g_cnt2[q][b], 1);
                g_list2[q][b*H2 + pos] = h;
            }
        }
        grid_sync();
    }

    // ---------- final readout for t=99 (parity 1) and output ----------
    for (int e = gtid; e < BB*OO; e += nth) {
        int b = e / OO, o = e - b*OO;
        int n = g_cnt2[1][b];
        const int* lst = &g_list2[1][b*H2];
        float io = 0.0f;
        for (int j = 0; j < n; j++) io += g_WoT[lst[j]*OO + o];
        float bo  = beta_out[o];
        float von = bo * g_vo[e] + (1.0f - bo) * io;
        float accf = g_acc[e] + von;
        out[e] = accf / 100.0f;    // divide by T
    }
}

// ---------------- launch ----------------
extern "C" void kernel_launch(void* const* d_in, const int* in_sizes, int n_in,
                              void* d_out, int out_size)
{
    const float* x         = (const float*)d_in[0];
    const float* W_delay   = (const float*)d_in[1];
    const float* delay_raw = (const float*)d_in[2];
    const float* W_rec1    = (const float*)d_in[3];
    const float* W2        = (const float*)d_in[4];
    const float* W_rec2    = (const float*)d_in[5];
    const float* W_out     = (const float*)d_in[6];
    const float* bn1_gamma = (const float*)d_in[7];
    const float* bn1_beta  = (const float*)d_in[8];
    const float* bn1_mean  = (const float*)d_in[9];
    const float* bn1_var   = (const float*)d_in[10];
    const float* bn2_gamma = (const float*)d_in[11];
    const float* bn2_beta  = (const float*)d_in[12];
    const float* bn2_mean  = (const float*)d_in[13];
    const float* bn2_var   = (const float*)d_in[14];
    const float* alpha1    = (const float*)d_in[15];
    const float* rho1      = (const float*)d_in[16];
    const float* beta_a1   = (const float*)d_in[17];
    const float* alpha2    = (const float*)d_in[18];
    const float* rho2      = (const float*)d_in[19];
    const float* beta_a2   = (const float*)d_in[20];
    const float* beta_out  = (const float*)d_in[21];

    prep_kernel<<<512, 256>>>(delay_raw, W_delay, W_rec1, W2, W_rec2, W_out,
                              bn1_gamma, bn1_beta, bn1_mean, bn1_var,
                              bn2_gamma, bn2_beta, bn2_mean, bn2_var);

    dim3 gg(H1/64, MT/64);   // (16, 400)
    gemm_p1_kernel<<<gg, 256>>>(x);

    snn_step_kernel<<<NBLK, NTHR>>>((float*)d_out,
                                    alpha1, rho1, beta_a1,
                                    alpha2, rho2, beta_a2,
                                    beta_out);
}

// round 2
// speedup vs baseline: 3.6114x; 3.6114x over previous
#include <cuda_runtime.h>
#include <cstdint>

#define BB 256
#define TT 100
#define CC 40
#define H1 1024
#define H2 512
#define OO 35

#define NCTA (BB/2)     // 128 CTAs, 2 batches each -> single wave
#define NTHR 1024

// ---------------- static device scratch (spike-path weights, BN-folded, transposed) ----
__device__ float g_Wr1T[H1 * H1];            // [in][out] * scale1[out]
__device__ float g_W2T [H1 * H2];            // [in][out] * scale2[out]
__device__ float g_Wr2T[H2 * H2];            // [in][out] * scale2[out]
__device__ float g_WoT [H2 * OO];            // [in][out]

// ---------------- prep: fold BN scale + transpose spike-path weights -------------------
__global__ void prep_kernel(const float* __restrict__ W_rec1,
                            const float* __restrict__ W2,
                            const float* __restrict__ W_rec2,
                            const float* __restrict__ W_out,
                            const float* __restrict__ g1, const float* __restrict__ v1,
                            const float* __restrict__ g2, const float* __restrict__ v2)
{
    const int gtid = blockIdx.x * blockDim.x + threadIdx.x;
    const int nth  = gridDim.x * blockDim.x;

    for (int i = gtid; i < H1*H1; i += nth) {
        int o = i >> 10, h = i & (H1-1);
        float sc = g1[o] * rsqrtf(v1[o] + 1e-5f);
        g_Wr1T[h*H1 + o] = W_rec1[i] * sc;
    }
    for (int i = gtid; i < H2*H1; i += nth) {   // W2 is [H2][H1]
        int o = i >> 10, h = i & (H1-1);
        float sc = g2[o] * rsqrtf(v2[o] + 1e-5f);
        g_W2T[h*H2 + o] = W2[i] * sc;
    }
    for (int i = gtid; i < H2*H2; i += nth) {
        int o = i >> 9, h = i & (H2-1);
        float sc = g2[o] * rsqrtf(v2[o] + 1e-5f);
        g_Wr2T[h*H2 + o] = W_rec2[i] * sc;
    }
    for (int i = gtid; i < OO*H2; i += nth) {   // W_out is [O][H2]
        int o = i / H2, h = i - o*H2;
        g_WoT[h*OO + o] = W_out[i];
    }
}

// ---------------- fused persistent SNN kernel: 1 CTA = 2 full batches -----------------
// All neuron state lives in registers; spike lists in shared memory; no grid sync.
__global__ __launch_bounds__(NTHR, 1) void snn_kernel(
    const float* __restrict__ x,
    const float* __restrict__ W_delay,
    const float* __restrict__ delay_raw,
    const float* __restrict__ bn1_gamma, const float* __restrict__ bn1_beta,
    const float* __restrict__ bn1_mean,  const float* __restrict__ bn1_var,
    const float* __restrict__ bn2_gamma, const float* __restrict__ bn2_beta,
    const float* __restrict__ bn2_mean,  const float* __restrict__ bn2_var,
    const float* __restrict__ alpha1, const float* __restrict__ rho1, const float* __restrict__ beta_a1,
    const float* __restrict__ alpha2, const float* __restrict__ rho2, const float* __restrict__ beta_a2,
    const float* __restrict__ beta_out,
    float* __restrict__ out)
{
    __shared__ int   s_fli[CC];
    __shared__ float s_frac[CC];
    __shared__ float s_xd[2][2][CC];       // [parity][bb][c] delayed input row
    __shared__ int   s_list1[2][2][H1];    // [parity][bb][...]
    __shared__ int   s_list2[2][2][H2];
    __shared__ int   s_cnt1[2][2];
    __shared__ int   s_cnt2[2][2];

    const int tid = threadIdx.x;
    const int b0  = blockIdx.x * 2;

    // delay params
    if (tid < CC) {
        float xr = delay_raw[tid];
        float s  = (xr >= 0.0f) ? (1.0f / (1.0f + expf(-xr)))
                                : (expf(xr) / (1.0f + expf(xr)));
        float d  = s * 30.0f;              // MAX_DELAY
        float fl = floorf(d);
        s_fli[tid]  = (int)fl;
        s_frac[tid] = d - fl;
    }
    if (tid < 4) { s_cnt1[tid >> 1][tid & 1] = 0; s_cnt2[tid >> 1][tid & 1] = 0; }

    // ---- layer-1 per-neuron constants (h = tid), W_delay row in registers ----
    const int h = tid;
    const float sc1    = bn1_gamma[h] * rsqrtf(bn1_var[h] + 1e-5f);
    const float shift1 = bn1_beta[h] - bn1_mean[h] * sc1;
    float W[CC];
    #pragma unroll
    for (int c = 0; c < CC; c++) W[c] = W_delay[h*CC + c] * sc1;
    const float al1 = alpha1[h], rh1 = rho1[h], ba1 = beta_a1[h];
    float v1a = 0.f, a1a = 0.f, s1a = 0.f;
    float v1b = 0.f, a1b = 0.f, s1b = 0.f;

    // ---- layer-2 per-neuron constants (bb2 = tid>>9, h2 = tid&511) ----
    const int bb2 = tid >> 9, h2 = tid & (H2 - 1);
    const float sc2    = bn2_gamma[h2] * rsqrtf(bn2_var[h2] + 1e-5f);
    const float shift2 = bn2_beta[h2] - bn2_mean[h2] * sc2;
    const float al2 = alpha2[h2], rh2 = rho2[h2], ba2 = beta_a2[h2];
    float v2 = 0.f, a2 = 0.f, s2 = 0.f;

    // ---- readout regs (threads 0..69: bb = tid/35, o = tid%35) ----
    float vo = 0.f, accv = 0.f, bo = 0.f;
    if (tid < 2*OO) bo = beta_out[tid % OO];

    __syncthreads();   // fli/frac + counters visible

    // delayed input row for t = 0
    if (tid < 2*CC) {
        int bb = tid / CC, c = tid - bb*CC;
        int i0 = 0 - s_fli[c];
        float fr = s_frac[c];
        const float* xb = x + (size_t)(b0 + bb) * TT * CC;
        float x0 = (i0 >= 0) ? xb[i0*CC + c]       : 0.0f;
        float x1 = (i0 >= 1) ? xb[(i0-1)*CC + c]   : 0.0f;
        s_xd[0][bb][c] = (1.0f - fr)*x0 + fr*x1;
    }
    __syncthreads();

    for (int t = 0; t < TT; t++) {
        const int q = t & 1, p = q ^ 1;

        // ---------- phase 1: layer 1 for both batches ----------
        float reca = 0.f, recb = 0.f;
        {
            int n = s_cnt1[p][0];
            const int* lst = s_list1[p][0];
            for (int j = 0; j < n; j++) reca += g_Wr1T[lst[j]*H1 + h];
            n = s_cnt1[p][1];
            lst = s_list1[p][1];
            for (int j = 0; j < n; j++) recb += g_Wr1T[lst[j]*H1 + h];
        }
        float Ia = shift1, Ib = shift1;
        #pragma unroll
        for (int c = 0; c < CC; c++) {
            Ia += W[c] * s_xd[q][0][c];
            Ib += W[c] * s_xd[q][1][c];
        }
        Ia += reca; Ib += recb;

        {   // batch a
            float an = rh1*a1a + ba1*s1a;
            float vn = al1*v1a + (1.0f - al1)*Ia - an - s1a;   // THRESH=1
            float sn = ((vn - 1.0f) >= 0.0f) ? 1.0f : 0.0f;
            a1a = an; v1a = vn; s1a = sn;
            if (sn != 0.0f) { int pos = atomicAdd(&s_cnt1[q][0], 1); s_list1[q][0][pos] = h; }
        }
        {   // batch b
            float an = rh1*a1b + ba1*s1b;
            float vn = al1*v1b + (1.0f - al1)*Ib - an - s1b;
            float sn = ((vn - 1.0f) >= 0.0f) ? 1.0f : 0.0f;
            a1b = an; v1b = vn; s1b = sn;
            if (sn != 0.0f) { int pos = atomicAdd(&s_cnt1[q][1], 1); s_list1[q][1][pos] = h; }
        }
        __syncthreads();   // sync 1: layer-1 spikes visible
        if (tid < 2) s_cnt1[p][tid] = 0;

        // ---------- phase 2: layer 2 ----------
        {
            float u = shift2;
            int n = s_cnt1[q][bb2];
            const int* l1 = s_list1[q][bb2];
            for (int j = 0; j < n; j++) u += g_W2T[l1[j]*H2 + h2];
            n = s_cnt2[p][bb2];
            const int* l2 = s_list2[p][bb2];
            for (int j = 0; j < n; j++) u += g_Wr2T[l2[j]*H2 + h2];

            float an = rh2*a2 + ba2*s2;
            float vn = al2*v2 + (1.0f - al2)*u - an - s2;
            float sn = ((vn - 1.0f) >= 0.0f) ? 1.0f : 0.0f;
            a2 = an; v2 = vn; s2 = sn;
            if (sn != 0.0f) { int pos = atomicAdd(&s_cnt2[q][bb2], 1); s_list2[q][bb2][pos] = h2; }
        }
        __syncthreads();   // sync 2: layer-2 spikes visible
        if (tid < 2) s_cnt2[p][tid] = 0;

        // ---------- phase 3: readout (threads 0..69) + prefetch xd for t+1 (threads 128..207) ----------
        if (tid < 2*OO) {
            int bb = tid / OO, o = tid - bb*OO;
            float io = 0.f;
            int n = s_cnt2[q][bb];
            const int* lst = s_list2[q][bb];
            for (int j = 0; j < n; j++) io += g_WoT[lst[j]*OO + o];
            vo = bo*vo + (1.0f - bo)*io;
            accv += vo;
        }
        if (t + 1 < TT && tid >= 128 && tid < 128 + 2*CC) {
            int k = tid - 128;
            int bb = k / CC, c = k - bb*CC;
            int i0 = (t + 1) - s_fli[c];
            float fr = s_frac[c];
            const float* xb = x + (size_t)(b0 + bb) * TT * CC;
            float x0 = (i0 >= 0) ? xb[i0*CC + c]     : 0.0f;
            float x1 = (i0 >= 1) ? xb[(i0-1)*CC + c] : 0.0f;
            s_xd[p][bb][c] = (1.0f - fr)*x0 + fr*x1;
        }
        __syncthreads();   // sync 3: xd[t+1] ready, list buffers safe to reuse
    }

    if (tid < 2*OO) {
        int bb = tid / OO, o = tid - bb*OO;
        out[(b0 + bb)*OO + o] = accv * (1.0f / (float)TT);
    }
}

// ---------------- launch ----------------
extern "C" void kernel_launch(void* const* d_in, const int* in_sizes, int n_in,
                              void* d_out, int out_size)
{
    const float* x         = (const float*)d_in[0];
    const float* W_delay   = (const float*)d_in[1];
    const float* delay_raw = (const float*)d_in[2];
    const float* W_rec1    = (const float*)d_in[3];
    const float* W2        = (const float*)d_in[4];
    const float* W_rec2    = (const float*)d_in[5];
    const float* W_out     = (const float*)d_in[6];
    const float* bn1_gamma = (const float*)d_in[7];
    const float* bn1_beta  = (const float*)d_in[8];
    const float* bn1_mean  = (const float*)d_in[9];
    const float* bn1_var   = (const float*)d_in[10];
    const float* bn2_gamma = (const float*)d_in[11];
    const float* bn2_beta  = (const float*)d_in[12];
    const float* bn2_mean  = (const float*)d_in[13];
    const float* bn2_var   = (const float*)d_in[14];
    const float* alpha1    = (const float*)d_in[15];
    const float* rho1      = (const float*)d_in[16];
    const float* beta_a1   = (const float*)d_in[17];
    const float* alpha2    = (const float*)d_in[18];
    const float* rho2      = (const float*)d_in[19];
    const float* beta_a2   = (const float*)d_in[20];
    const float* beta_out  = (const float*)d_in[21];

    prep_kernel<<<512, 256>>>(W_rec1, W2, W_rec2, W_out,
                              bn1_gamma, bn1_var, bn2_gamma, bn2_var);

    snn_kernel<<<NCTA, NTHR>>>(x, W_delay, delay_raw,
                               bn1_gamma, bn1_beta, bn1_mean, bn1_var,
                               bn2_gamma, bn2_beta, bn2_mean, bn2_var,
                               alpha1, rho1, beta_a1,
                               alpha2, rho2, beta_a2,
                               beta_out,
                               (float*)d_out);
}

// round 3
// speedup vs baseline: 4.4654x; 1.2365x over previous
#include <cuda_runtime.h>
#include <cstdint>

#define BB 256
#define TT 100
#define CC 40
#define H1 1024
#define H2 512
#define OO 35
#define MT (BB*TT)

#define NCTA (BB/2)     // 128 CTAs, 2 batches each
#define NTHR 1024

// ---------------- static device scratch ----------------
__device__ float g_P1[(size_t)MT * H1];      // precomputed BN-folded input drive
__device__ float g_Wr1T[H1 * H1];            // [in][out] * scale1[out]
__device__ float g_W2T [H1 * H2];            // [in][out] * scale2[out]
__device__ float g_Wr2T[H2 * H2];            // [in][out] * scale2[out]
__device__ float g_WoT [H2 * OO];            // [in][out]

// ---------------- f32x2 packed helpers ----------------
__device__ __forceinline__ uint64_t pack2(float lo, float hi) {
    uint64_t r;
    asm("mov.b64 %0, {%1, %2};" : "=l"(r) : "r"(__float_as_uint(lo)), "r"(__float_as_uint(hi)));
    return r;
}
__device__ __forceinline__ uint64_t dup2(float v) {
    uint64_t r;
    asm("mov.b64 %0, {%1, %1};" : "=l"(r) : "r"(__float_as_uint(v)));
    return r;
}
__device__ __forceinline__ uint64_t fma2(uint64_t a, uint64_t b, uint64_t c) {
    uint64_t d;
    asm("fma.rn.f32x2 %0, %1, %2, %3;" : "=l"(d) : "l"(a), "l"(b), "l"(c));
    return d;
}
__device__ __forceinline__ uint64_t add2(uint64_t a, uint64_t b) {
    uint64_t d;
    asm("add.rn.f32x2 %0, %1, %2;" : "=l"(d) : "l"(a), "l"(b));
    return d;
}
__device__ __forceinline__ float2 unpack2(uint64_t v) {
    uint32_t lo, hi;
    asm("mov.b64 {%0, %1}, %2;" : "=r"(lo), "=r"(hi) : "l"(v));
    return make_float2(__uint_as_float(lo), __uint_as_float(hi));
}

// ---------------- prep: coalesced tiled transposes with BN scale folding --------------
// z=0: W_rec1 [1024x1024] * sc1 -> g_Wr1T ; z=1: W2 [512x1024] * sc2 -> g_W2T
// z=2: W_rec2 [512x512]  * sc2 -> g_Wr2T ; z=3: W_out [35x512]        -> g_WoT
__global__ void prep_kernel(const float* __restrict__ W_rec1,
                            const float* __restrict__ W2,
                            const float* __restrict__ W_rec2,
                            const float* __restrict__ W_out,
                            const float* __restrict__ g1, const float* __restrict__ v1,
                            const float* __restrict__ g2, const float* __restrict__ v2)
{
    __shared__ float tile[32][33];
    const int z = blockIdx.z;

    const float* src; float* dst; const float* sg; const float* sv;
    int R, Cc;                       // src is [R rows(o)][Cc cols(h)]
    if      (z == 0) { src = W_rec1; dst = g_Wr1T; R = H1; Cc = H1; sg = g1; sv = v1; }
    else if (z == 1) { src = W2;     dst = g_W2T;  R = H2; Cc = H1; sg = g2; sv = v2; }
    else if (z == 2) { src = W_rec2; dst = g_Wr2T; R = H2; Cc = H2; sg = g2; sv = v2; }
    else             { src = W_out;  dst = g_WoT;  R = OO; Cc = H2; sg = nullptr; sv = nullptr; }

    const int x0 = blockIdx.x * 32;  // over cols h
    const int y0 = blockIdx.y * 32;  // over rows o
    if (x0 >= Cc || y0 >= R) return;

    const int tx = threadIdx.x, ty = threadIdx.y;   // (32, 8)

    #pragma unroll
    for (int k = 0; k < 4; k++) {
        int o = y0 + ty + 8*k;
        int h = x0 + tx;
        if (o < R && h < Cc) {
            float sc = sg ? (sg[o] * rsqrtf(sv[o] + 1e-5f)) : 1.0f;
            tile[ty + 8*k][tx] = src[(size_t)o * Cc + h] * sc;
        }
    }
    __syncthreads();
    #pragma unroll
    for (int k = 0; k < 4; k++) {
        int h = x0 + ty + 8*k;
        int o = y0 + tx;
        if (h < Cc && o < R) dst[(size_t)h * R + o] = tile[tx][ty + 8*k];
    }
}

// ---------------- P1 GEMM: 128x128 tile, 256 thr, 8x8/thread, f32x2 packed ------------
// P1[r=t*256+b][h] = sum_c xd[r,c] * (W_delay[h,c]*sc1[h]) + shift1[h]
__global__ __launch_bounds__(256) void gemm_p1_kernel(
    const float* __restrict__ x,
    const float* __restrict__ W_delay,
    const float* __restrict__ delay_raw,
    const float* __restrict__ g1, const float* __restrict__ b1,
    const float* __restrict__ m1, const float* __restrict__ v1)
{
    __shared__ float xs[CC][128];
    __shared__ float ws[CC][128];
    __shared__ float sc1s[128], sh1s[128];
    __shared__ int   fli[CC];
    __shared__ float frac[CC];

    const int tid = threadIdx.x;
    const int h0  = blockIdx.x * 128;
    const int r0  = blockIdx.y * 128;

    if (tid < CC) {
        float xr = delay_raw[tid];
        float s  = (xr >= 0.0f) ? (1.0f / (1.0f + expf(-xr)))
                                : (expf(xr) / (1.0f + expf(xr)));
        float d  = s * 30.0f;
        float fl = floorf(d);
        fli[tid]  = (int)fl;
        frac[tid] = d - fl;
    }
    if (tid < 128) {
        int hh = h0 + tid;
        float sc = g1[hh] * rsqrtf(v1[hh] + 1e-5f);
        sc1s[tid] = sc;
        sh1s[tid] = b1[hh] - m1[hh] * sc;
    }
    __syncthreads();

    #pragma unroll
    for (int i = tid; i < 128 * CC; i += 256) {
        int j = i / CC, c = i - j * CC;
        ws[c][j] = W_delay[(h0 + j) * CC + c] * sc1s[j];
    }
    #pragma unroll
    for (int i = tid; i < 128 * CC; i += 256) {
        int row = i / CC, c = i - row * CC;
        int r = r0 + row;
        int t = r >> 8;
        int b = r & 255;
        int i0 = t - fli[c];
        float fr = frac[c];
        const float* xb = x + (size_t)b * TT * CC;
        float x0v = (i0 >= 0) ? xb[i0 * CC + c]       : 0.0f;
        float x1v = (i0 >= 1) ? xb[(i0 - 1) * CC + c] : 0.0f;
        xs[c][row] = (1.0f - fr) * x0v + fr * x1v;
    }
    __syncthreads();

    const int ty = tid >> 4;        // 0..15 -> rows ty*8..+7
    const int tx = tid & 15;        // 0..15 -> cols tx*8..+7

    uint64_t acc[8][4];
    #pragma unroll
    for (int i = 0; i < 8; i++)
        #pragma unroll
        for (int j = 0; j < 4; j++) acc[i][j] = 0ULL;

    #pragma unroll
    for (int k = 0; k < CC; k++) {
        float4 A0 = *(const float4*)&xs[k][ty * 8];
        float4 A1 = *(const float4*)&xs[k][ty * 8 + 4];
        float4 W0 = *(const float4*)&ws[k][tx * 8];
        float4 W1 = *(const float4*)&ws[k][tx * 8 + 4];
        uint64_t w01 = pack2(W0.x, W0.y);
        uint64_t w23 = pack2(W0.z, W0.w);
        uint64_t w45 = pack2(W1.x, W1.y);
        uint64_t w67 = pack2(W1.z, W1.w);
        float av[8] = {A0.x, A0.y, A0.z, A0.w, A1.x, A1.y, A1.z, A1.w};
        #pragma unroll
        for (int ii = 0; ii < 8; ii++) {
            uint64_t ad = dup2(av[ii]);
            acc[ii][0] = fma2(ad, w01, acc[ii][0]);
            acc[ii][1] = fma2(ad, w23, acc[ii][1]);
            acc[ii][2] = fma2(ad, w45, acc[ii][2]);
            acc[ii][3] = fma2(ad, w67, acc[ii][3]);
        }
    }

    uint64_t sh0 = pack2(sh1s[tx*8+0], sh1s[tx*8+1]);
    uint64_t sh1 = pack2(sh1s[tx*8+2], sh1s[tx*8+3]);
    uint64_t sh2 = pack2(sh1s[tx*8+4], sh1s[tx*8+5]);
    uint64_t sh3 = pack2(sh1s[tx*8+6], sh1s[tx*8+7]);

    #pragma unroll
    for (int ii = 0; ii < 8; ii++) {
        int r = r0 + ty * 8 + ii;
        float2 p0 = unpack2(add2(acc[ii][0], sh0));
        float2 p1 = unpack2(add2(acc[ii][1], sh1));
        float2 p2 = unpack2(add2(acc[ii][2], sh2));
        float2 p3 = unpack2(add2(acc[ii][3], sh3));
        float4 o0 = make_float4(p0.x, p0.y, p1.x, p1.y);
        float4 o1 = make_float4(p2.x, p2.y, p3.x, p3.y);
        *(float4*)&g_P1[(size_t)r * H1 + h0 + tx * 8]     = o0;
        *(float4*)&g_P1[(size_t)r * H1 + h0 + tx * 8 + 4] = o1;
    }
}

// ---------------- step kernel: 1 CTA = 2 batches, state in regs, 2 syncs/step ---------
__global__ __launch_bounds__(NTHR, 1) void snn_kernel(
    const float* __restrict__ bn2_gamma, const float* __restrict__ bn2_beta,
    const float* __restrict__ bn2_mean,  const float* __restrict__ bn2_var,
    const float* __restrict__ alpha1, const float* __restrict__ rho1, const float* __restrict__ beta_a1,
    const float* __restrict__ alpha2, const float* __restrict__ rho2, const float* __restrict__ beta_a2,
    const float* __restrict__ beta_out,
    float* __restrict__ out)
{
    __shared__ int s_list1[2][2][H1];
    __shared__ int s_list2[2][2][H2];
    __shared__ int s_cnt1[2][2];
    __shared__ int s_cnt2[2][2];

    const int tid = threadIdx.x;
    const int b0  = blockIdx.x * 2;

    if (tid < 4) { s_cnt1[tid >> 1][tid & 1] = 0; s_cnt2[tid >> 1][tid & 1] = 0; }

    // layer-1: h = tid, both batches
    const int h = tid;
    const float al1 = alpha1[h], rh1 = rho1[h], ba1 = beta_a1[h];
    float v1a = 0.f, a1a = 0.f, s1a = 0.f;
    float v1b = 0.f, a1b = 0.f, s1b = 0.f;

    // layer-2: bb2 = tid>>9, h2 = tid&511
    const int bb2 = tid >> 9, h2 = tid & (H2 - 1);
    const float sc2    = bn2_gamma[h2] * rsqrtf(bn2_var[h2] + 1e-5f);
    const float shift2 = bn2_beta[h2] - bn2_mean[h2] * sc2;
    const float al2 = alpha2[h2], rh2 = rho2[h2], ba2 = beta_a2[h2];
    float v2 = 0.f, a2 = 0.f, s2 = 0.f;

    // readout (threads 0..69)
    float vo = 0.f, accv = 0.f, bo = 0.f;
    if (tid < 2 * OO) bo = beta_out[tid % OO];

    float pa = g_P1[(size_t)b0 * H1 + h];
    float pb = g_P1[(size_t)(b0 + 1) * H1 + h];
    __syncthreads();

    for (int t = 0; t < TT; t++) {
        const int q = t & 1, p = q ^ 1;

        // ---------- phase 1: layer 1, both batches ----------
        float reca = 0.f, recb = 0.f;
        {
            int n = s_cnt1[p][0];
            const int* lst = s_list1[p][0];
            for (int j = 0; j < n; j++) reca += g_Wr1T[lst[j] * H1 + h];
            n = s_cnt1[p][1];
            lst = s_list1[p][1];
            for (int j = 0; j < n; j++) recb += g_Wr1T[lst[j] * H1 + h];
        }
        {
            float I = pa + reca;
            float an = rh1 * a1a + ba1 * s1a;
            float vn = al1 * v1a + (1.0f - al1) * I - an - s1a;   // THRESH=1
            float sn = ((vn - 1.0f) >= 0.0f) ? 1.0f : 0.0f;
            a1a = an; v1a = vn; s1a = sn;
            if (sn != 0.0f) { int pos = atomicAdd(&s_cnt1[q][0], 1); s_list1[q][0][pos] = h; }
        }
        {
            float I = pb + recb;
            float an = rh1 * a1b + ba1 * s1b;
            float vn = al1 * v1b + (1.0f - al1) * I - an - s1b;
            float sn = ((vn - 1.0f) >= 0.0f) ? 1.0f : 0.0f;
            a1b = an; v1b = vn; s1b = sn;
            if (sn != 0.0f) { int pos = atomicAdd(&s_cnt1[q][1], 1); s_list1[q][1][pos] = h; }
        }
        // prefetch P1 for t+1 (consumed after 2 syncs -> latency hidden)
        float pan = 0.f, pbn = 0.f;
        if (t + 1 < TT) {
            pan = g_P1[(size_t)((t + 1) * BB + b0) * H1 + h];
            pbn = g_P1[(size_t)((t + 1) * BB + b0 + 1) * H1 + h];
        }
        __syncthreads();                   // sync 1: layer-1 spikes visible
        if (tid < 2) s_cnt1[p][tid] = 0;

        // ---------- phase 2: layer 2 ----------
        {
            float u = shift2;
            int n = s_cnt1[q][bb2];
            const int* l1 = s_list1[q][bb2];
            for (int j = 0; j < n; j++) u += g_W2T[l1[j] * H2 + h2];
            n = s_cnt2[p][bb2];
            const int* l2 = s_list2[p][bb2];
            for (int j = 0; j < n; j++) u += g_Wr2T[l2[j] * H2 + h2];

            float an = rh2 * a2 + ba2 * s2;
            float vn = al2 * v2 + (1.0f - al2) * u - an - s2;
            float sn = ((vn - 1.0f) >= 0.0f) ? 1.0f : 0.0f;
            a2 = an; v2 = vn; s2 = sn;
            if (sn != 0.0f) { int pos = atomicAdd(&s_cnt2[q][bb2], 1); s_list2[q][bb2][pos] = h2; }
        }
        __syncthreads();                   // sync 2: layer-2 spikes visible
        if (tid < 2) s_cnt2[p][tid] = 0;

        // ---------- phase 3 (unsynced tail): readout for step t ----------
        if (tid < 2 * OO) {
            int bb = tid / OO, o = tid - bb * OO;
            float io = 0.f;
            int n = s_cnt2[q][bb];
            const int* lst = s_list2[q][bb];
            for (int j = 0; j < n; j++) io += g_WoT[lst[j] * OO + o];
            vo = bo * vo + (1.0f - bo) * io;
            accv += vo;
        }
        pa = pan; pb = pbn;
    }

    if (tid < 2 * OO) {
        int bb = tid / OO, o = tid - bb * OO;
        out[(b0 + bb) * OO + o] = accv * (1.0f / (float)TT);
    }
}

// ---------------- launch ----------------
extern "C" void kernel_launch(void* const* d_in, const int* in_sizes, int n_in,
                              void* d_out, int out_size)
{
    const float* x         = (const float*)d_in[0];
    const float* W_delay   = (const float*)d_in[1];
    const float* delay_raw = (const float*)d_in[2];
    const float* W_rec1    = (const float*)d_in[3];
    const float* W2        = (const float*)d_in[4];
    const float* W_rec2    = (const float*)d_in[5];
    const float* W_out     = (const float*)d_in[6];
    const float* bn1_gamma = (const float*)d_in[7];
    const float* bn1_beta  = (const float*)d_in[8];
    const float* bn1_mean  = (const float*)d_in[9];
    const float* bn1_var   = (const float*)d_in[10];
    const float* bn2_gamma = (const float*)d_in[11];
    const float* bn2_beta  = (const float*)d_in[12];
    const float* bn2_mean  = (const float*)d_in[13];
    const float* bn2_var   = (const float*)d_in[14];
    const float* alpha1    = (const float*)d_in[15];
    const float* rho1      = (const float*)d_in[16];
    const float* beta_a1   = (const float*)d_in[17];
    const float* alpha2    = (const float*)d_in[18];
    const float* rho2      = (const float*)d_in[19];
    const float* beta_a2   = (const float*)d_in[20];
    const float* beta_out  = (const float*)d_in[21];

    dim3 pb(32, 8);
    dim3 pg(32, 32, 4);
    prep_kernel<<<pg, pb>>>(W_rec1, W2, W_rec2, W_out,
                            bn1_gamma, bn1_var, bn2_gamma, bn2_var);

    dim3 gg(H1 / 128, MT / 128);   // (8, 200)
    gemm_p1_kernel<<<gg, 256>>>(x, W_delay, delay_raw,
                                bn1_gamma, bn1_beta, bn1_mean, bn1_var);

    snn_kernel<<<NCTA, NTHR>>>(bn2_gamma, bn2_beta, bn2_mean, bn2_var,
                               alpha1, rho1, beta_a1,
                               alpha2, rho2, beta_a2,
                               beta_out,
                               (float*)d_out);
}